// round 12
// baseline (speedup 1.0000x reference)
#include <cuda_runtime.h>
#include <cuda_bf16.h>

// PepEmbedding: out[b,h,:] = soft_threshold(emb[x[b,h],:], s[x[b,h],:])
//   soft_threshold(v,s) = sign(v)*relu(|v| - sigmoid(s))
//
// R12: gather untouched (MLP=4, 32-bit offsets — pinned at ~84% DRAM / 956MB
// compulsory floor). Binning fused to ONE kernel: per-block smem histogram ->
// publish counts -> software grid barrier (all 200 blocks co-resident:
// 32 warps + 53KB smem = 2 blocks/SM, capacity 296) -> deterministic prefix
// recompute (R11 logic, proven) -> coalesced bucket-grouped key writes.
// Barrier is graph-replay-safe: monotonic cohort counter, no reset needed.

#define ROWS        (16384 * 50)     // 819,200
#define NBUCKETS    256
#define BUCKET_SHIFT 12              // idx >> 12 -> bucket 0..244
#define NBLK        200              // 819200 / 4096
#define RPB         4096             // rows per binning block
#define QBLK        50               // NBLK / 4
#define VEC_PER_ROW 32               // 128 floats / float4

typedef unsigned long long ull;

// Scratch (device globals — allocation is forbidden)
__device__ int cnt[NBLK * NBUCKETS];      // per-block bucket counts
__device__ ull sorted_key[ROWS];          // (idx << 32) | row
__device__ unsigned long long bar_ctr;    // monotonic grid-barrier counter

// ------------------------------ fused: hist + grid barrier + prefix + scatter
__global__ __launch_bounds__(1024)
void k_bin(const int4* __restrict__ x4) {
    __shared__ int cnt_loc[NBUCKETS];
    __shared__ int loff[NBUCKETS];
    __shared__ int gstart[NBUCKETS];
    __shared__ int tA[NBUCKETS];
    __shared__ int pre_s[NBUCKETS];
    __shared__ int part_tot[4][NBUCKETS];
    __shared__ int part_pre[4][NBUCKETS];
    __shared__ ull keys[RPB];             // 32 KB
    __shared__ int gpos[RPB];             // 16 KB

    int t = threadIdx.x;
    if (t < NBUCKETS) cnt_loc[t] = 0;
    __syncthreads();

    // ---- local histogram + ranks (4 rows/thread via one int4 load)
    int base = blockIdx.x * RPB;
    int4 v = x4[blockIdx.x * 1024 + t];
    int idx0 = v.x, idx1 = v.y, idx2 = v.z, idx3 = v.w;
    int b0 = idx0 >> BUCKET_SHIFT;
    int b1 = idx1 >> BUCKET_SHIFT;
    int b2 = idx2 >> BUCKET_SHIFT;
    int b3 = idx3 >> BUCKET_SHIFT;
    int lr0 = atomicAdd(&cnt_loc[b0], 1);
    int lr1 = atomicAdd(&cnt_loc[b1], 1);
    int lr2 = atomicAdd(&cnt_loc[b2], 1);
    int lr3 = atomicAdd(&cnt_loc[b3], 1);
    __syncthreads();

    // ---- publish this block's counts, then grid barrier
    if (t < NBUCKETS) cnt[blockIdx.x * NBUCKETS + t] = cnt_loc[t];
    __threadfence();                       // make cnt row globally visible
    __syncthreads();
    if (t == 0) {
        unsigned long long arrive = atomicAdd(&bar_ctr, 1ull) + 1ull;
        unsigned long long target = ((arrive + (NBLK - 1)) / NBLK) * NBLK;
        while (atomicAdd(&bar_ctr, 0ull) < target)  // cohort barrier, no reset
            __nanosleep(64);
    }
    __syncthreads();
    __threadfence();                       // acquire peers' cnt writes

    // ---- recompute global prefixes from cnt (deterministic, R11 logic)
    {
        int q   = t >> 8;                  // 0..3
        int bkt = t & 255;
        int tot = 0, pre = 0;
        int bid = blockIdx.x;
        #pragma unroll 10
        for (int b = q * QBLK; b < (q + 1) * QBLK; b++) {
            int c = cnt[b * NBUCKETS + bkt];
            tot += c;
            if (b < bid) pre += c;
        }
        part_tot[q][bkt] = tot;
        part_pre[q][bkt] = pre;
    }
    __syncthreads();

    int myA = 0;
    if (t < NBUCKETS) {
        int T = part_tot[0][t] + part_tot[1][t] + part_tot[2][t] + part_tot[3][t];
        int P = part_pre[0][t] + part_pre[1][t] + part_pre[2][t] + part_pre[3][t];
        tA[t]    = T;
        pre_s[t] = P;
        myA = cnt_loc[t];
        loff[t] = myA;
    }
    __syncthreads();

    // ---- dual Hillis-Steele scans: tA (cross-bucket), loff (local)
    #pragma unroll
    for (int off = 1; off < NBUCKETS; off <<= 1) {
        int vA = (t < NBUCKETS && t >= off) ? tA[t - off] : 0;
        int vL = (t < NBUCKETS && t >= off) ? loff[t - off] : 0;
        __syncthreads();
        if (t < NBUCKETS) { tA[t] += vA; loff[t] += vL; }
        __syncthreads();
    }
    if (t < NBUCKETS) {
        int T = part_tot[0][t] + part_tot[1][t] + part_tot[2][t] + part_tot[3][t];
        gstart[t] = (tA[t] - T) + pre_s[t];   // excl bucket base + block prefix
        loff[t]  -= myA;                      // exclusive local
    }
    __syncthreads();

    // ---- group keys by bucket in smem; record final global positions
    int r = base + 4 * t;
    int s0 = loff[b0] + lr0;
    int s1 = loff[b1] + lr1;
    int s2 = loff[b2] + lr2;
    int s3 = loff[b3] + lr3;
    keys[s0] = ((ull)(unsigned)idx0 << 32) | (unsigned)(r + 0);
    keys[s1] = ((ull)(unsigned)idx1 << 32) | (unsigned)(r + 1);
    keys[s2] = ((ull)(unsigned)idx2 << 32) | (unsigned)(r + 2);
    keys[s3] = ((ull)(unsigned)idx3 << 32) | (unsigned)(r + 3);
    gpos[s0] = gstart[b0] + lr0;
    gpos[s1] = gstart[b1] + lr1;
    gpos[s2] = gstart[b2] + lr2;
    gpos[s3] = gstart[b3] + lr3;
    __syncthreads();

    // ---- coalesced-run writes (consecutive slots/bucket -> consecutive gpos)
    #pragma unroll
    for (int k = 0; k < 4; k++)
        sorted_key[gpos[t + k * 1024]] = keys[t + k * 1024];
}

// ---------------------------------------------------------------- gather
__device__ __forceinline__ float soft_thresh(float v, float sv) {
    float t = __fdividef(1.0f, 1.0f + __expf(-sv));
    float m = fmaxf(fabsf(v) - t, 0.0f);
    return copysignf(m, v);
}

__device__ __forceinline__ float4 soft_thresh4(float4 v, float4 t) {
    float4 o;
    o.x = soft_thresh(v.x, t.x);
    o.y = soft_thresh(v.y, t.y);
    o.z = soft_thresh(v.z, t.z);
    o.w = soft_thresh(v.w, t.w);
    return o;
}

__global__ __launch_bounds__(256, 8)
void k_gather(const float4* __restrict__ emb,
              const float4* __restrict__ s,
              float4* __restrict__ out) {
    // one warp = TWO consecutive sorted rows -> 4 independent loads per thread
    unsigned gid  = blockIdx.x * 256u + threadIdx.x;
    unsigned warp = gid >> 5;
    unsigned comp = gid & 31u;

    ulonglong2 kk = __ldg((const ulonglong2*)&sorted_key[warp * 2]); // uniform
    unsigned row0 = (unsigned)(kk.x & 0xffffffffu);
    unsigned idx0 = (unsigned)(kk.x >> 32);
    unsigned row1 = (unsigned)(kk.y & 0xffffffffu);
    unsigned idx1 = (unsigned)(kk.y >> 32);

    unsigned off0 = idx0 * (unsigned)VEC_PER_ROW + comp;
    unsigned off1 = idx1 * (unsigned)VEC_PER_ROW + comp;

    // 4 independent 16B loads in flight (MLP=4 — measured sweet spot)
    float4 v0 = __ldg(&emb[off0]);
    float4 t0 = __ldg(&s[off0]);
    float4 v1 = __ldg(&emb[off1]);
    float4 t1 = __ldg(&s[off1]);

    __stcs(&out[row0 * (unsigned)VEC_PER_ROW + comp], soft_thresh4(v0, t0));
    __stcs(&out[row1 * (unsigned)VEC_PER_ROW + comp], soft_thresh4(v1, t1));
}

// ---------------------------------------------------------------- launch
extern "C" void kernel_launch(void* const* d_in, const int* in_sizes, int n_in,
                              void* d_out, int out_size) {
    const int4*   x4  = (const int4*)d_in[0];
    const float4* emb = (const float4*)d_in[1];
    const float4* s   = (const float4*)d_in[2];
    float4*       out = (float4*)d_out;

    k_bin   <<<NBLK, 1024>>>(x4);
    k_gather<<<ROWS / 16, 256>>>(emb, s, out);
}

// round 14
// speedup vs baseline: 1.0042x; 1.0042x over previous
#include <cuda_runtime.h>
#include <cuda_bf16.h>

// PepEmbedding: out[b,h,:] = soft_threshold(emb[x[b,h],:], s[x[b,h],:])
//   soft_threshold(v,s) = sign(v)*relu(|v| - sigmoid(s))
//
// R14: gather untouched (MLP=4, 32-bit offsets — ~84% DRAM at the 956MB
// compulsory floor). Binning rebuilt around the R8/R13 root cause: block-level
// range reservation IS valid, but cursors must start at the scanned bucket
// BASES (global positions), not 0. Chain: tiny hist -> 1-block scan (cursor =
// bases, resets totals for graph replays) -> fused re-hist + reserve + rank +
// direct key writes. No prefix matrices, no 48KB staging. Within-bucket order
// is nondeterministic (like R2, which passed): out[row] depends only on row's
// own index.

#define ROWS        (16384 * 50)     // 819,200
#define NBUCKETS    256
#define BUCKET_SHIFT 12              // idx >> 12 -> bucket 0..244
#define NBLK        200              // 819200 / 4096
#define RPB         4096             // rows per binning block
#define VEC_PER_ROW 32               // 128 floats / float4

typedef unsigned long long ull;

// Scratch (device globals — allocation is forbidden; zero-init at load)
__device__ int bucket_total[NBUCKETS];   // summed by k_hist, reset by k_scan
__device__ int bucket_cursor[NBUCKETS];  // set to bases by k_scan each launch
__device__ ull sorted_key[ROWS];         // (idx << 32) | row

// ---------------------------------------------------------------- 1) histogram
__global__ __launch_bounds__(1024)
void k_hist(const int4* __restrict__ x4) {
    __shared__ int h[NBUCKETS];
    if (threadIdx.x < NBUCKETS) h[threadIdx.x] = 0;
    __syncthreads();

    int4 v = x4[blockIdx.x * 1024 + threadIdx.x];   // 4 indices, coalesced 16B
    atomicAdd(&h[v.x >> BUCKET_SHIFT], 1);
    atomicAdd(&h[v.y >> BUCKET_SHIFT], 1);
    atomicAdd(&h[v.z >> BUCKET_SHIFT], 1);
    atomicAdd(&h[v.w >> BUCKET_SHIFT], 1);
    __syncthreads();

    if (threadIdx.x < NBUCKETS && h[threadIdx.x])
        atomicAdd(&bucket_total[threadIdx.x], h[threadIdx.x]);
}

// ------------------------------- 2) scan totals -> cursor bases (+ replay reset)
__global__ __launch_bounds__(NBUCKETS)
void k_scan() {
    __shared__ int tmp[NBUCKETS];
    int t = threadIdx.x;
    int v = bucket_total[t];
    tmp[t] = v;
    __syncthreads();
    #pragma unroll
    for (int off = 1; off < NBUCKETS; off <<= 1) {
        int u = (t >= off) ? tmp[t - off] : 0;
        __syncthreads();
        tmp[t] += u;
        __syncthreads();
    }
    bucket_cursor[t] = tmp[t] - v;   // exclusive base (THE R8/R13 fix)
    bucket_total[t]  = 0;            // ready for next graph replay
}

// ------------------------- 3) fused re-hist + reserve + rank + direct scatter
__global__ __launch_bounds__(1024)
void k_bin(const int4* __restrict__ x4) {
    __shared__ int h[NBUCKETS];       // block-local counts (pass 1)
    __shared__ int h2[NBUCKETS];      // rank counters (pass 2)
    __shared__ int gbase[NBUCKETS];   // reserved global base per bucket

    int t = threadIdx.x;
    if (t < NBUCKETS) { h[t] = 0; h2[t] = 0; }
    __syncthreads();

    int4 v = x4[blockIdx.x * 1024 + t];
    int b0 = v.x >> BUCKET_SHIFT;
    int b1 = v.y >> BUCKET_SHIFT;
    int b2 = v.z >> BUCKET_SHIFT;
    int b3 = v.w >> BUCKET_SHIFT;
    atomicAdd(&h[b0], 1);
    atomicAdd(&h[b1], 1);
    atomicAdd(&h[b2], 1);
    atomicAdd(&h[b3], 1);
    __syncthreads();

    // reserve a contiguous global range per non-empty bucket
    if (t < NBUCKETS) {
        int c = h[t];
        if (c > 0) gbase[t] = atomicAdd(&bucket_cursor[t], c);
    }
    __syncthreads();

    // rank + direct write into reserved runs (avg 16 keys = 128B contiguous)
    unsigned r = (unsigned)(blockIdx.x * RPB + 4 * t);
    int lr0 = atomicAdd(&h2[b0], 1);
    sorted_key[gbase[b0] + lr0] = ((ull)(unsigned)v.x << 32) | (r + 0u);
    int lr1 = atomicAdd(&h2[b1], 1);
    sorted_key[gbase[b1] + lr1] = ((ull)(unsigned)v.y << 32) | (r + 1u);
    int lr2 = atomicAdd(&h2[b2], 1);
    sorted_key[gbase[b2] + lr2] = ((ull)(unsigned)v.z << 32) | (r + 2u);
    int lr3 = atomicAdd(&h2[b3], 1);
    sorted_key[gbase[b3] + lr3] = ((ull)(unsigned)v.w << 32) | (r + 3u);
}

// ---------------------------------------------------------------- 4) gather
__device__ __forceinline__ float soft_thresh(float v, float sv) {
    float t = __fdividef(1.0f, 1.0f + __expf(-sv));
    float m = fmaxf(fabsf(v) - t, 0.0f);
    return copysignf(m, v);
}

__device__ __forceinline__ float4 soft_thresh4(float4 v, float4 t) {
    float4 o;
    o.x = soft_thresh(v.x, t.x);
    o.y = soft_thresh(v.y, t.y);
    o.z = soft_thresh(v.z, t.z);
    o.w = soft_thresh(v.w, t.w);
    return o;
}

__global__ __launch_bounds__(256, 8)
void k_gather(const float4* __restrict__ emb,
              const float4* __restrict__ s,
              float4* __restrict__ out) {
    // one warp = TWO consecutive sorted rows -> 4 independent loads per thread
    unsigned gid  = blockIdx.x * 256u + threadIdx.x;
    unsigned warp = gid >> 5;
    unsigned comp = gid & 31u;

    ulonglong2 kk = __ldg((const ulonglong2*)&sorted_key[warp * 2]); // uniform
    unsigned row0 = (unsigned)(kk.x & 0xffffffffu);
    unsigned idx0 = (unsigned)(kk.x >> 32);
    unsigned row1 = (unsigned)(kk.y & 0xffffffffu);
    unsigned idx1 = (unsigned)(kk.y >> 32);

    unsigned off0 = idx0 * (unsigned)VEC_PER_ROW + comp;
    unsigned off1 = idx1 * (unsigned)VEC_PER_ROW + comp;

    // 4 independent 16B loads in flight (MLP=4 — measured sweet spot)
    float4 v0 = __ldg(&emb[off0]);
    float4 t0 = __ldg(&s[off0]);
    float4 v1 = __ldg(&emb[off1]);
    float4 t1 = __ldg(&s[off1]);

    __stcs(&out[row0 * (unsigned)VEC_PER_ROW + comp], soft_thresh4(v0, t0));
    __stcs(&out[row1 * (unsigned)VEC_PER_ROW + comp], soft_thresh4(v1, t1));
}

// ---------------------------------------------------------------- launch
extern "C" void kernel_launch(void* const* d_in, const int* in_sizes, int n_in,
                              void* d_out, int out_size) {
    const int4*   x4  = (const int4*)d_in[0];
    const float4* emb = (const float4*)d_in[1];
    const float4* s   = (const float4*)d_in[2];
    float4*       out = (float4*)d_out;

    k_hist<<<NBLK, 1024>>>(x4);
    k_scan<<<1, NBUCKETS>>>();
    k_bin <<<NBLK, 1024>>>(x4);

    // ROWS/2 warps, 8 warps per 256-thread block
    k_gather<<<ROWS / 16, 256>>>(emb, s, out);
}